// round 11
// baseline (speedup 1.0000x reference)
#include <cuda_runtime.h>
#include <cuda_bf16.h>
#include <cstdint>
#include <math.h>

#define B_ 64
#define S_ 512
#define E_ 512
#define H_ 8
#define D_ 64
#define L_ 4
#define O_ 1000
#define KW_ 5
#define STRIDE_ 5
#define LOUT_ 102
#define BH_ (B_*H_)
#define M_ (B_*S_)   /* 32768 */

typedef __nv_bfloat16 bf16;

// ---------------- scratch ----------------------------------------------------
__device__ float g_out[M_*E_];              // fp32 master activations [B,S,E]
__device__ float g_mh[M_*E_];               // attention block output (fp32)
__device__ float g_pooled[B_*LOUT_];
__device__ bf16  g_outb[M_*E_];             // bf16 shadow of g_out
__device__ bf16  g_qb[M_*E_];               // [B,S,H*D]
__device__ bf16  g_kb[M_*E_];               // [B,S,H*D]
__device__ bf16  g_vtb[M_*E_];              // [B,H,D,S]
__device__ bf16  g_catb[M_*E_];             // [B,S,H*D]
__device__ bf16  g_ffb[M_*2*E_];            // FFN hidden
#define LWT_ 2097152
__device__ bf16  g_wtb[(size_t)L_*LWT_];    // transposed bf16 weights per layer
#define QT_  0
#define KT_  262144
#define VTW_ 524288
#define OT_  786432
#define W1T_ 1048576
#define W2T_ 1572864

// ---------------- helpers -----------------------------------------------------
__device__ __forceinline__ uint32_t smem_u32(const void* p) {
    uint32_t a;
    asm("{ .reg .u64 t; cvta.to.shared.u64 t, %1; cvt.u32.u64 %0, t; }" : "=r"(a) : "l"(p));
    return a;
}
__device__ __forceinline__ void cp_async16(uint32_t dst, const void* src) {
    asm volatile("cp.async.cg.shared.global [%0], [%1], 16;" :: "r"(dst), "l"(src) : "memory");
}
__device__ __forceinline__ void cp_commit() {
    asm volatile("cp.async.commit_group;" ::: "memory");
}
__device__ __forceinline__ void cp_wait0() {
    asm volatile("cp.async.wait_group 0;" ::: "memory");
}
__device__ __forceinline__ void cp_wait1() {
    asm volatile("cp.async.wait_group 1;" ::: "memory");
}
__device__ __forceinline__ void mma_bf16(float* c, const uint32_t* a, const uint32_t* b) {
    asm volatile(
        "mma.sync.aligned.m16n8k16.row.col.f32.bf16.bf16.f32 "
        "{%0,%1,%2,%3}, {%4,%5,%6,%7}, {%8,%9}, {%0,%1,%2,%3};"
        : "+f"(c[0]), "+f"(c[1]), "+f"(c[2]), "+f"(c[3])
        : "r"(a[0]), "r"(a[1]), "r"(a[2]), "r"(a[3]), "r"(b[0]), "r"(b[1]));
}
__device__ __forceinline__ void ldsm4(uint32_t* r, uint32_t addr) {
    asm volatile("ldmatrix.sync.aligned.m8n8.x4.shared.b16 {%0,%1,%2,%3}, [%4];"
        : "=r"(r[0]), "=r"(r[1]), "=r"(r[2]), "=r"(r[3]) : "r"(addr));
}
__device__ __forceinline__ uint32_t packbf(float a, float b) {
    __nv_bfloat162 h = __floats2bfloat162_rn(a, b);
    return *(uint32_t*)&h;
}

// ---------------- bf16 mma GEMM ----------------------------------------------
// CTA tile 256x128, k-chunk 64, 3-stage cp.async pipeline.
// 8 warps as 4(m) x 2(n); warp tile 64x64; ldmatrix fragment loads.
// MODE: 0=PROJ->bf16(bias), 1=VPROJT->bf16(bias along m, [B,H,D,S] scatter),
//       2=WO->fp32(bias), 4=FFN1->bf16(bias+relu), 5=FFN2->fp32+bf16(bias+resid)
struct GB {
    const bf16* A; const bf16* Bm;
    const float* bias; const float* resid;
    float* Cf; bf16* Cb;
    int lda, ldb, ldc;
};

#define GSA 36
#define AST (256 * GSA)   /* words per A stage */
#define BST (128 * GSA)   /* words per B stage */
static const int SMEM_G = 3 * (AST + BST) * 4;   // 165888 B

__device__ __forceinline__ void gloadA(uint32_t* dst, const bf16* src, int ld, int koff) {
    const int t = threadIdx.x;
    #pragma unroll
    for (int i = 0; i < 8; i++) {
        int idx = t + i * 256;
        int r = idx >> 3, c8 = idx & 7;
        cp_async16(smem_u32(dst + r * GSA + c8 * 4), src + (size_t)r * ld + koff + c8 * 8);
    }
}
__device__ __forceinline__ void gloadB(uint32_t* dst, const bf16* src, int ld, int koff) {
    const int t = threadIdx.x;
    #pragma unroll
    for (int i = 0; i < 4; i++) {
        int idx = t + i * 256;
        int r = idx >> 3, c8 = idx & 7;
        cp_async16(smem_u32(dst + r * GSA + c8 * 4), src + (size_t)r * ld + koff + c8 * 8);
    }
}

template<int MODE, int NC>
__global__ __launch_bounds__(256, 1) void gemmB(GB g) {
    extern __shared__ uint32_t smw[];
    const uint32_t SB = smem_u32(smw);

    const int tid = threadIdx.x, w = tid >> 5, lane = tid & 31;
    const int gq = lane >> 2, q = lane & 3;
    const int lr = lane & 15, lc = (lane >> 4) * 4;   // ldmatrix row / word-chunk
    const int wm = (w >> 1) * 64, wn = (w & 1) * 64;
    const int m0 = blockIdx.y * 256, n0 = blockIdx.x * 128;
    const bf16* Ab = g.A + (size_t)m0 * g.lda;
    const bf16* Bb = g.Bm + (size_t)n0 * g.ldb;

    const uint32_t aOff = ((wm + lr) * GSA + lc) * 4;
    const uint32_t bOff = ((wn + lr) * GSA + lc) * 4;

    float c[4][8][4];
    #pragma unroll
    for (int mt = 0; mt < 4; mt++)
        #pragma unroll
        for (int nt = 0; nt < 8; nt++)
            #pragma unroll
            for (int j = 0; j < 4; j++) c[mt][nt][j] = 0.0f;

    gloadA(smw, Ab, g.lda, 0);
    gloadB(smw + 3 * AST, Bb, g.ldb, 0);
    cp_commit();
    gloadA(smw + AST, Ab, g.lda, 64);
    gloadB(smw + 3 * AST + BST, Bb, g.ldb, 64);
    cp_commit();

    #pragma unroll 1
    for (int ch = 0; ch < NC; ch++) {
        const int st = ch % 3;
        if (ch + 1 < NC) cp_wait1(); else cp_wait0();
        __syncthreads();
        if (ch + 2 < NC) {
            const int nx = (ch + 2) % 3;
            gloadA(smw + nx * AST, Ab, g.lda, (ch + 2) * 64);
            gloadB(smw + 3 * AST + nx * BST, Bb, g.ldb, (ch + 2) * 64);
            cp_commit();
        }
        const uint32_t Ab_s = SB + st * (AST * 4) + aOff;
        const uint32_t Bb_s = SB + (3 * AST + st * BST) * 4 + bOff;
        #pragma unroll
        for (int ks = 0; ks < 4; ks++) {
            uint32_t a[4][4], b[4][4];
            #pragma unroll
            for (int mt = 0; mt < 4; mt++)
                ldsm4(a[mt], Ab_s + mt * (16 * GSA * 4) + ks * 32);
            #pragma unroll
            for (int nt = 0; nt < 4; nt++)
                ldsm4(b[nt], Bb_s + nt * (16 * GSA * 4) + ks * 32);
            #pragma unroll
            for (int mt = 0; mt < 4; mt++) {
                #pragma unroll
                for (int nt = 0; nt < 4; nt++) {
                    uint32_t b0[2] = { b[nt][0], b[nt][2] };
                    uint32_t b1[2] = { b[nt][1], b[nt][3] };
                    mma_bf16(c[mt][nt * 2],     a[mt], b0);
                    mma_bf16(c[mt][nt * 2 + 1], a[mt], b1);
                }
            }
        }
    }

    // ------------- epilogue ---------------------------------------------------
    #pragma unroll
    for (int mt = 0; mt < 4; mt++) {
        #pragma unroll
        for (int nt = 0; nt < 8; nt++) {
            const int m = m0 + wm + mt * 16 + gq;
            const int n = n0 + wn + nt * 8 + 2 * q;
            float v00 = c[mt][nt][0], v01 = c[mt][nt][1];
            float v10 = c[mt][nt][2], v11 = c[mt][nt][3];
            if (MODE == 1) {
                float bm0 = g.bias[m], bm1 = g.bias[m + 8];
                v00 += bm0; v01 += bm0; v10 += bm1; v11 += bm1;
                // m = h*64+d (global d), n = b*512+s ; C[B,H,D,S]
                size_t base = ((size_t)(n >> 9) * 8 + (m >> 6)) * 32768 +
                              (size_t)(m & 63) * 512 + (n & 511);
                ((uint32_t*)g.Cb)[base >> 1]                = packbf(v00, v01);
                ((uint32_t*)g.Cb)[(base + 8 * 512) >> 1]    = packbf(v10, v11);
            } else {
                float bx = g.bias[n], by = g.bias[n + 1];
                v00 += bx; v01 += by; v10 += bx; v11 += by;
                if (MODE == 4) {
                    v00 = fmaxf(v00, 0.f); v01 = fmaxf(v01, 0.f);
                    v10 = fmaxf(v10, 0.f); v11 = fmaxf(v11, 0.f);
                }
                if (MODE == 5) {
                    const float* r0 = g.resid + (size_t)m * g.ldc + n;
                    const float* r1 = g.resid + (size_t)(m + 8) * g.ldc + n;
                    v00 += r0[0]; v01 += r0[1]; v10 += r1[0]; v11 += r1[1];
                }
                size_t e0 = (size_t)m * g.ldc + n;
                size_t e1 = (size_t)(m + 8) * g.ldc + n;
                if (MODE == 2 || MODE == 5) {
                    float2 o0 = { v00, v01 }, o1 = { v10, v11 };
                    *(float2*)(g.Cf + e0) = o0;
                    *(float2*)(g.Cf + e1) = o1;
                }
                if (MODE == 0 || MODE == 4 || MODE == 5) {
                    ((uint32_t*)g.Cb)[e0 >> 1] = packbf(v00, v01);
                    ((uint32_t*)g.Cb)[e1 >> 1] = packbf(v10, v11);
                }
            }
        }
    }
}

// ---------------- fused flash attention (bf16 + ldmatrix) ---------------------
// grid (S_/128, BH_), 256 thr. K tiles 128x64 bf16, Vt 64x128 bf16, P 128x128 bf16.
#define FSK 36
#define FSV 68
#define FSP 68
#define FL_WORDS (2*128*FSK + 2*64*FSV + 128*FSP)   /* 26624 words */
#define FL_SMEM  (FL_WORDS * 4)                      /* 106496 B */

__global__ __launch_bounds__(256) void flashB(float scale) {
    extern __shared__ uint32_t smw[];
    uint32_t* Ks[2] = { smw, smw + 128 * FSK };
    uint32_t* Vs[2] = { smw + 2 * 128 * FSK, smw + 2 * 128 * FSK + 64 * FSV };
    uint32_t* Ps = smw + 2 * 128 * FSK + 2 * 64 * FSV;
    const uint32_t PsB = smem_u32(Ps);

    const int tid = threadIdx.x, w = tid >> 5, lane = tid & 31;
    const int gq = lane >> 2, q = lane & 3;
    const int lr = lane & 15, lc = (lane >> 4) * 4;
    const int z = blockIdx.y, b = z >> 3, h = z & 7;
    const int q0 = blockIdx.x * 128;

    const bf16* Qg = g_qb + ((size_t)b * S_ + q0) * E_ + h * 64;
    const bf16* Kg = g_kb + (size_t)b * S_ * E_ + h * 64;
    const bf16* Vg = g_vtb + (size_t)z * (64 * S_);

    // stage Q (128 x 64 bf16) into Ps
    #pragma unroll
    for (int i = 0; i < 4; i++) {
        int idx = tid + i * 256;
        int r = idx >> 3, c8 = idx & 7;
        cp_async16(smem_u32(Ps + r * FSP + c8 * 4), Qg + (size_t)r * E_ + c8 * 8);
    }
    cp_commit();
    // K/V tile 0
    #pragma unroll
    for (int i = 0; i < 4; i++) {
        int idx = tid + i * 256;
        int r = idx >> 3, c8 = idx & 7;
        cp_async16(smem_u32(Ks[0] + r * FSK + c8 * 4), Kg + (size_t)r * E_ + c8 * 8);
    }
    #pragma unroll
    for (int i = 0; i < 4; i++) {
        int idx = tid + i * 256;
        int r = idx >> 4, c16 = idx & 15;
        cp_async16(smem_u32(Vs[0] + r * FSV + c16 * 4), Vg + (size_t)r * S_ + c16 * 8);
    }
    cp_commit();

    cp_wait1();
    __syncthreads();

    uint32_t qf[4][4];
    {
        uint32_t base = PsB + ((w * 16 + lr) * FSP + lc) * 4;
        #pragma unroll
        for (int ks = 0; ks < 4; ks++) ldsm4(qf[ks], base + ks * 32);
    }

    float o[8][4];
    #pragma unroll
    for (int i = 0; i < 8; i++)
        #pragma unroll
        for (int j = 0; j < 4; j++) o[i][j] = 0.0f;
    float mr0 = -1e30f, mr1 = -1e30f, l0 = 0.0f, l1 = 0.0f;

    #pragma unroll 1
    for (int kt = 0; kt < 4; kt++) {
        const int cur = kt & 1;
        cp_wait0();
        __syncthreads();
        if (kt < 3) {
            const int nxt = cur ^ 1;
            const bf16* Kn = Kg + (size_t)(kt + 1) * 128 * E_;
            #pragma unroll
            for (int i = 0; i < 4; i++) {
                int idx = tid + i * 256;
                int r = idx >> 3, c8 = idx & 7;
                cp_async16(smem_u32(Ks[nxt] + r * FSK + c8 * 4), Kn + (size_t)r * E_ + c8 * 8);
            }
            const bf16* Vn = Vg + (kt + 1) * 128;
            #pragma unroll
            for (int i = 0; i < 4; i++) {
                int idx = tid + i * 256;
                int r = idx >> 4, c16 = idx & 15;
                cp_async16(smem_u32(Vs[nxt] + r * FSV + c16 * 4), Vn + (size_t)r * S_ + c16 * 8);
            }
            cp_commit();
        }

        // ---- S = Q @ K^T ----
        const uint32_t KsB = smem_u32(Ks[cur]) + (lr * FSK + lc) * 4;
        float s[16][4];
        #pragma unroll
        for (int nf = 0; nf < 16; nf++)
            #pragma unroll
            for (int j = 0; j < 4; j++) s[nf][j] = 0.0f;
        #pragma unroll
        for (int ks = 0; ks < 4; ks++) {
            #pragma unroll
            for (int nf2 = 0; nf2 < 8; nf2++) {
                uint32_t bm[4];
                ldsm4(bm, KsB + nf2 * (16 * FSK * 4) + ks * 32);
                uint32_t b0[2] = { bm[0], bm[2] };
                uint32_t b1[2] = { bm[1], bm[3] };
                mma_bf16(s[nf2 * 2],     qf[ks], b0);
                mma_bf16(s[nf2 * 2 + 1], qf[ks], b1);
            }
        }

        // ---- scale + row max ----
        float mt0 = -1e30f, mt1 = -1e30f;
        #pragma unroll
        for (int nf = 0; nf < 16; nf++) {
            s[nf][0] *= scale; s[nf][1] *= scale;
            s[nf][2] *= scale; s[nf][3] *= scale;
            mt0 = fmaxf(mt0, fmaxf(s[nf][0], s[nf][1]));
            mt1 = fmaxf(mt1, fmaxf(s[nf][2], s[nf][3]));
        }
        mt0 = fmaxf(mt0, __shfl_xor_sync(0xFFFFFFFFu, mt0, 1));
        mt0 = fmaxf(mt0, __shfl_xor_sync(0xFFFFFFFFu, mt0, 2));
        mt1 = fmaxf(mt1, __shfl_xor_sync(0xFFFFFFFFu, mt1, 1));
        mt1 = fmaxf(mt1, __shfl_xor_sync(0xFFFFFFFFu, mt1, 2));

        float mn0 = fmaxf(mr0, mt0), mn1 = fmaxf(mr1, mt1);
        float al0 = __expf(mr0 - mn0), al1 = __expf(mr1 - mn1);

        // ---- P = exp(S-m) -> bf16 pairs into Ps (warp-local rows), row sums ----
        float sum0 = 0.0f, sum1 = 0.0f;
        int prow = (w * 16 + gq) * FSP + q;
        #pragma unroll
        for (int nf = 0; nf < 16; nf++) {
            float p0 = __expf(s[nf][0] - mn0), p1 = __expf(s[nf][1] - mn0);
            float p2 = __expf(s[nf][2] - mn1), p3 = __expf(s[nf][3] - mn1);
            sum0 += p0 + p1; sum1 += p2 + p3;
            Ps[prow + nf * 4]           = packbf(p0, p1);
            Ps[prow + nf * 4 + 8 * FSP] = packbf(p2, p3);
        }
        sum0 += __shfl_xor_sync(0xFFFFFFFFu, sum0, 1);
        sum0 += __shfl_xor_sync(0xFFFFFFFFu, sum0, 2);
        sum1 += __shfl_xor_sync(0xFFFFFFFFu, sum1, 1);
        sum1 += __shfl_xor_sync(0xFFFFFFFFu, sum1, 2);
        l0 = l0 * al0 + sum0;
        l1 = l1 * al1 + sum1;
        mr0 = mn0; mr1 = mn1;

        #pragma unroll
        for (int nf2 = 0; nf2 < 8; nf2++) {
            o[nf2][0] *= al0; o[nf2][1] *= al0;
            o[nf2][2] *= al1; o[nf2][3] *= al1;
        }
        __syncwarp();

        // ---- O += P @ V ----
        const uint32_t PsA = PsB + ((w * 16 + lr) * FSP + lc) * 4;
        const uint32_t VsB = smem_u32(Vs[cur]) + (lr * FSV + lc) * 4;
        #pragma unroll
        for (int ks2 = 0; ks2 < 8; ks2++) {
            uint32_t aa[4];
            ldsm4(aa, PsA + ks2 * 32);
            #pragma unroll
            for (int nf4 = 0; nf4 < 4; nf4++) {
                uint32_t bm[4];
                ldsm4(bm, VsB + nf4 * (16 * FSV * 4) + ks2 * 32);
                uint32_t b0[2] = { bm[0], bm[2] };
                uint32_t b1[2] = { bm[1], bm[3] };
                mma_bf16(o[nf4 * 2],     aa, b0);
                mma_bf16(o[nf4 * 2 + 1], aa, b1);
            }
        }
        __syncwarp();
    }

    // ---- epilogue: O / l -> g_catb[b, s, h*64+d] (bf16) ----
    float li0 = 1.0f / l0, li1 = 1.0f / l1;
    const int m = q0 + w * 16 + gq;
    size_t base0 = ((size_t)b * S_ + m) * E_ + h * 64 + 2 * q;
    size_t base1 = base0 + (size_t)8 * E_;
    #pragma unroll
    for (int nf2 = 0; nf2 < 8; nf2++) {
        ((uint32_t*)g_catb)[(base0 + nf2 * 8) >> 1] = packbf(o[nf2][0] * li0, o[nf2][1] * li0);
        ((uint32_t*)g_catb)[(base1 + nf2 * 8) >> 1] = packbf(o[nf2][2] * li1, o[nf2][3] * li1);
    }
}

// ---------------- weight transpose+convert: src [K,N] fp32 -> dst [N,K] bf16 --
__global__ void transpose_kernel(const float* __restrict__ src, bf16* __restrict__ dst,
                                 int K, int N) {
    __shared__ float t[32][33];
    int z = blockIdx.z;
    src += (size_t)z * K * N;
    dst += (size_t)z * N * K;
    int n0 = blockIdx.x * 32, k0 = blockIdx.y * 32;
    for (int i = threadIdx.y; i < 32; i += 8)
        t[i][threadIdx.x] = src[(size_t)(k0 + i) * N + n0 + threadIdx.x];
    __syncthreads();
    for (int i = threadIdx.y; i < 32; i += 8)
        dst[(size_t)(n0 + i) * K + k0 + threadIdx.x] = __float2bfloat16(t[threadIdx.x][i]);
}

// ---------------- embedding gather + mask (fp32 + bf16) -----------------------
__global__ void embed_kernel(const int* __restrict__ tokens, const float* __restrict__ emb) {
    int gid = blockIdx.x * 256 + threadIdx.x;   // over M*E/4
    int idx = gid * 4;
    int m = idx >> 9;
    int e = idx & 511;
    int t = tokens[m];
    float4 v = { 0.f, 0.f, 0.f, 0.f };
    if (t > 0) v = *(const float4*)(emb + (size_t)t * E_ + e);
    *(float4*)(g_out + idx) = v;
    uint2 hb = { packbf(v.x, v.y), packbf(v.z, v.w) };
    ((uint2*)g_outb)[gid] = hb;
}

// ---------------- residual add + l2 normalize (128 thr, float4) ---------------
__global__ void addnorm_kernel() {
    int row = blockIdx.x;
    float4* o4 = (float4*)(g_out + (size_t)row * E_);
    const float4* m4 = (const float4*)(g_mh + (size_t)row * E_);
    int t = threadIdx.x;
    float4 a = o4[t], m = m4[t];
    a.x += m.x; a.y += m.y; a.z += m.z; a.w += m.w;
    float sq = a.x * a.x + a.y * a.y + a.z * a.z + a.w * a.w;
    #pragma unroll
    for (int o = 16; o; o >>= 1) sq += __shfl_xor_sync(0xFFFFFFFFu, sq, o);
    __shared__ float red[4];
    if ((t & 31) == 0) red[t >> 5] = sq;
    __syncthreads();
    float inv = rsqrtf(fmaxf(red[0] + red[1] + red[2] + red[3], 1e-12f));
    a.x *= inv; a.y *= inv; a.z *= inv; a.w *= inv;
    o4[t] = a;
    uint2 hb = { packbf(a.x, a.y), packbf(a.z, a.w) };
    ((uint2*)g_outb)[(size_t)row * 128 + t] = hb;
}

// ---------------- conv1d(KW=5, stride=5) -------------------------------------
__global__ void conv_kernel(const float* __restrict__ Wc, const float* __restrict__ bc) {
    int b = blockIdx.x / LOUT_;
    int j = blockIdx.x % LOUT_;
    const float* base = g_out + ((size_t)b * S_ + j * STRIDE_) * E_;
    float acc = 0.0f;
    for (int i = threadIdx.x; i < KW_ * E_; i += 256)
        acc += base[i] * Wc[i];
    __shared__ float red[256];
    red[threadIdx.x] = acc;
    __syncthreads();
    for (int s = 128; s > 0; s >>= 1) {
        if (threadIdx.x < s) red[threadIdx.x] += red[threadIdx.x + s];
        __syncthreads();
    }
    if (threadIdx.x == 0) g_pooled[b * LOUT_ + j] = red[0] + bc[0];
}

// ---------------- final dense + softmax over 1000 ----------------------------
__global__ void dense_softmax_kernel(const float* __restrict__ Wd,
                                     const float* __restrict__ bd,
                                     float* __restrict__ outp) {
    int b = blockIdx.x;
    __shared__ float p[LOUT_];
    int t = threadIdx.x;
    if (t < LOUT_) p[t] = g_pooled[b * LOUT_ + t];
    __syncthreads();

    float lg[4];
    #pragma unroll
    for (int u = 0; u < 4; u++) {
        int o = t + u * 256;
        float acc = -1e30f;
        if (o < O_) {
            acc = bd[o];
            for (int j = 0; j < LOUT_; j++)
                acc += p[j] * Wd[j * O_ + o];
        }
        lg[u] = acc;
    }
    __shared__ float red[256];
    float m = fmaxf(fmaxf(lg[0], lg[1]), fmaxf(lg[2], lg[3]));
    red[t] = m;
    __syncthreads();
    for (int s = 128; s > 0; s >>= 1) {
        if (t < s) red[t] = fmaxf(red[t], red[t + s]);
        __syncthreads();
    }
    float mx = red[0];
    __syncthreads();
    float e[4], sum = 0.0f;
    #pragma unroll
    for (int u = 0; u < 4; u++) {
        e[u] = expf(lg[u] - mx);
        sum += e[u];
    }
    red[t] = sum;
    __syncthreads();
    for (int s = 128; s > 0; s >>= 1) {
        if (t < s) red[t] += red[t + s];
        __syncthreads();
    }
    float inv = 1.0f / red[0];
    #pragma unroll
    for (int u = 0; u < 4; u++) {
        int o = t + u * 256;
        if (o < O_) outp[(size_t)b * O_ + o] = e[u] * inv;
    }
}

// ---------------- host launcher ----------------------------------------------
extern "C" void kernel_launch(void* const* d_in, const int* in_sizes, int n_in,
                              void* d_out, int out_size) {
    const int*   tokens = (const int*)  d_in[0];
    const float* emb    = (const float*)d_in[1];
    const float* Wq     = (const float*)d_in[2];
    const float* bq     = (const float*)d_in[3];
    const float* Wk     = (const float*)d_in[4];
    const float* bk     = (const float*)d_in[5];
    const float* Wv     = (const float*)d_in[6];
    const float* bv     = (const float*)d_in[7];
    const float* Wo     = (const float*)d_in[8];
    const float* bo     = (const float*)d_in[9];
    const float* W1     = (const float*)d_in[10];
    const float* b1     = (const float*)d_in[11];
    const float* W2     = (const float*)d_in[12];
    const float* b2     = (const float*)d_in[13];
    const float* Wc     = (const float*)d_in[14];
    const float* bc     = (const float*)d_in[15];
    const float* Wd     = (const float*)d_in[16];
    const float* bd     = (const float*)d_in[17];
    float* outp = (float*)d_out;
    (void)in_sizes; (void)n_in; (void)out_size;

    float *p_out, *p_mh;
    bf16 *p_outb, *p_qb, *p_kb, *p_vtb, *p_catb, *p_ffb, *p_wtb;
    cudaGetSymbolAddress((void**)&p_out,  g_out);
    cudaGetSymbolAddress((void**)&p_mh,   g_mh);
    cudaGetSymbolAddress((void**)&p_outb, g_outb);
    cudaGetSymbolAddress((void**)&p_qb,   g_qb);
    cudaGetSymbolAddress((void**)&p_kb,   g_kb);
    cudaGetSymbolAddress((void**)&p_vtb,  g_vtb);
    cudaGetSymbolAddress((void**)&p_catb, g_catb);
    cudaGetSymbolAddress((void**)&p_ffb,  g_ffb);
    cudaGetSymbolAddress((void**)&p_wtb,  g_wtb);

    cudaFuncSetAttribute(gemmB<0,8>,  cudaFuncAttributeMaxDynamicSharedMemorySize, SMEM_G);
    cudaFuncSetAttribute(gemmB<1,8>,  cudaFuncAttributeMaxDynamicSharedMemorySize, SMEM_G);
    cudaFuncSetAttribute(gemmB<2,8>,  cudaFuncAttributeMaxDynamicSharedMemorySize, SMEM_G);
    cudaFuncSetAttribute(gemmB<4,8>,  cudaFuncAttributeMaxDynamicSharedMemorySize, SMEM_G);
    cudaFuncSetAttribute(gemmB<5,16>, cudaFuncAttributeMaxDynamicSharedMemorySize, SMEM_G);
    cudaFuncSetAttribute(flashB,      cudaFuncAttributeMaxDynamicSharedMemorySize, FL_SMEM);

    const float scale = 0.044194173824159216f;  // 1/sqrt(512)
    dim3 tthr(32, 8);

    // ---- pre-transpose+convert all weights to bf16 [N,K] ----
    for (int i = 0; i < L_; i++) {
        bf16* wt = p_wtb + (size_t)i * LWT_;
        transpose_kernel<<<dim3(2, 16, 8), tthr>>>(Wq + (size_t)i*H_*E_*D_, wt + QT_,  512, 64);
        transpose_kernel<<<dim3(2, 16, 8), tthr>>>(Wk + (size_t)i*H_*E_*D_, wt + KT_,  512, 64);
        transpose_kernel<<<dim3(2, 16, 8), tthr>>>(Wv + (size_t)i*H_*E_*D_, wt + VTW_, 512, 64);
        transpose_kernel<<<dim3(16, 16, 1), tthr>>>(Wo + (size_t)i*E_*E_,   wt + OT_,  512, 512);
        transpose_kernel<<<dim3(32, 16, 1), tthr>>>(W1 + (size_t)i*E_*2*E_, wt + W1T_, 512, 1024);
        transpose_kernel<<<dim3(16, 32, 1), tthr>>>(W2 + (size_t)i*2*E_*E_, wt + W2T_, 1024, 512);
    }

    embed_kernel<<<(M_ * E_) / 1024, 256>>>(tokens, emb);

    for (int i = 0; i < L_; i++) {
        bf16* wt = p_wtb + (size_t)i * LWT_;
        GB a;

        // Q = out @ Wq^T + bq  -> bf16 [B,S,H*D]
        a = { p_outb, wt + QT_, bq + (size_t)i*512, nullptr, nullptr, p_qb, 512, 512, 512 };
        gemmB<0,8><<<dim3(4, 128), 256, SMEM_G>>>(a);
        // K
        a = { p_outb, wt + KT_, bk + (size_t)i*512, nullptr, nullptr, p_kb, 512, 512, 512 };
        gemmB<0,8><<<dim3(4, 128), 256, SMEM_G>>>(a);
        // V^T = Wv^T @ out^T + bv  -> bf16 [B,H,D,S]  (A=weights, B=activations)
        a = { wt + VTW_, p_outb, bv + (size_t)i*512, nullptr, nullptr, p_vtb, 512, 512, 0 };
        gemmB<1,8><<<dim3(256, 2), 256, SMEM_G>>>(a);

        // fused attention -> g_catb (bf16)
        flashB<<<dim3(S_/128, BH_), 256, FL_SMEM>>>(scale);

        // mh = cat @ Wo^T + bo  -> fp32
        a = { p_catb, wt + OT_, bo + (size_t)i*512, nullptr, p_mh, nullptr, 512, 512, 512 };
        gemmB<2,8><<<dim3(4, 128), 256, SMEM_G>>>(a);

        addnorm_kernel<<<M_, 128>>>();

        // ff = relu(out @ W1^T + b1)  -> bf16
        a = { p_outb, wt + W1T_, b1 + (size_t)i*1024, nullptr, nullptr, p_ffb, 512, 512, 1024 };
        gemmB<4,8><<<dim3(8, 128), 256, SMEM_G>>>(a);

        // out = ff @ W2^T + b2 + out  -> fp32 + bf16
        a = { p_ffb, wt + W2T_, b2 + (size_t)i*512, p_out, p_out, p_outb, 1024, 1024, 512 };
        gemmB<5,16><<<dim3(4, 128), 256, SMEM_G>>>(a);
    }

    conv_kernel<<<B_ * LOUT_, 256>>>(Wc, bc);
    dense_softmax_kernel<<<B_, 256>>>(Wd, bd, outp);
}

// round 12
// speedup vs baseline: 1.1793x; 1.1793x over previous
#include <cuda_runtime.h>
#include <cuda_bf16.h>
#include <cstdint>
#include <math.h>

#define B_ 64
#define S_ 512
#define E_ 512
#define H_ 8
#define D_ 64
#define L_ 4
#define O_ 1000
#define KW_ 5
#define STRIDE_ 5
#define LOUT_ 102
#define BH_ (B_*H_)
#define M_ (B_*S_)   /* 32768 */

typedef __nv_bfloat16 bf16;

// ---------------- scratch ----------------------------------------------------
__device__ float g_out[M_*E_];              // fp32 master activations [B,S,E]
__device__ float g_mh[M_*E_];               // attention block output (fp32)
__device__ float g_pooled[B_*LOUT_];
__device__ bf16  g_outb[M_*E_];             // bf16 shadow of g_out
__device__ bf16  g_qb[M_*E_];               // [B,S,H*D]
__device__ bf16  g_kb[M_*E_];               // [B,S,H*D]
__device__ bf16  g_vtb[M_*E_];              // [B,H,D,S]
__device__ bf16  g_catb[M_*E_];             // [B,S,H*D]
__device__ bf16  g_ffb[M_*2*E_];            // FFN hidden
#define LWT_ 2097152
__device__ bf16  g_wtb[(size_t)L_*LWT_];    // transposed bf16 weights per layer
#define QT_  0
#define KT_  262144
#define VTW_ 524288
#define OT_  786432
#define W1T_ 1048576
#define W2T_ 1572864

// ---------------- helpers -----------------------------------------------------
__device__ __forceinline__ uint32_t smem_u32(const void* p) {
    uint32_t a;
    asm("{ .reg .u64 t; cvta.to.shared.u64 t, %1; cvt.u32.u64 %0, t; }" : "=r"(a) : "l"(p));
    return a;
}
__device__ __forceinline__ void cp_async16(uint32_t dst, const void* src) {
    asm volatile("cp.async.cg.shared.global [%0], [%1], 16;" :: "r"(dst), "l"(src) : "memory");
}
__device__ __forceinline__ void cp_commit() {
    asm volatile("cp.async.commit_group;" ::: "memory");
}
__device__ __forceinline__ void cp_wait0() {
    asm volatile("cp.async.wait_group 0;" ::: "memory");
}
__device__ __forceinline__ void cp_wait1() {
    asm volatile("cp.async.wait_group 1;" ::: "memory");
}
__device__ __forceinline__ void mma_bf16(float* c, const uint32_t* a, const uint32_t* b) {
    asm volatile(
        "mma.sync.aligned.m16n8k16.row.col.f32.bf16.bf16.f32 "
        "{%0,%1,%2,%3}, {%4,%5,%6,%7}, {%8,%9}, {%0,%1,%2,%3};"
        : "+f"(c[0]), "+f"(c[1]), "+f"(c[2]), "+f"(c[3])
        : "r"(a[0]), "r"(a[1]), "r"(a[2]), "r"(a[3]), "r"(b[0]), "r"(b[1]));
}
__device__ __forceinline__ void ldsm4(uint32_t* r, uint32_t addr) {
    asm volatile("ldmatrix.sync.aligned.m8n8.x4.shared.b16 {%0,%1,%2,%3}, [%4];"
        : "=r"(r[0]), "=r"(r[1]), "=r"(r[2]), "=r"(r[3]) : "r"(addr));
}
__device__ __forceinline__ uint32_t packbf(float a, float b) {
    __nv_bfloat162 h = __floats2bfloat162_rn(a, b);
    return *(uint32_t*)&h;
}

// ---------------- bf16 mma GEMM ----------------------------------------------
// CTA tile 128x128, k-chunk 64, 3-stage cp.async ring, 2 CTAs/SM.
// 8 warps as 2(m) x 4(n); warp tile 64x32; ldmatrix fragment loads.
// MODE: 0=PROJ->bf16(bias), 1=VPROJT->bf16(bias along m, [B,H,D,S] scatter),
//       2=WO->fp32(bias), 4=FFN1->bf16(bias+relu), 5=FFN2->fp32+bf16(bias+resid),
//       6=QK merged (N=1024: n<512 -> Cb/bias, else Cb2/bias2)
struct GB {
    const bf16* A; const bf16* Bm;
    const float* bias; const float* resid;
    float* Cf; bf16* Cb;
    const float* bias2; bf16* Cb2;
    int lda, ldb, ldc;
};

#define GSA 36
#define GST (128 * GSA)   /* words per stage (A or B) */
static const int SMEM_G = 6 * GST * 4;   // 110592 B -> 2 CTAs/SM

__device__ __forceinline__ void gload(uint32_t* dst, const bf16* src, int ld, int koff) {
    const int t = threadIdx.x;
    #pragma unroll
    for (int i = 0; i < 4; i++) {
        int idx = t + i * 256;
        int r = idx >> 3, c8 = idx & 7;
        cp_async16(smem_u32(dst + r * GSA + c8 * 4), src + (size_t)r * ld + koff + c8 * 8);
    }
}

template<int MODE, int NC>
__global__ __launch_bounds__(256, 2) void gemmB(GB g) {
    extern __shared__ uint32_t smw[];
    const uint32_t SB = smem_u32(smw);

    const int tid = threadIdx.x, w = tid >> 5, lane = tid & 31;
    const int gq = lane >> 2, q = lane & 3;
    const int lr = lane & 15, lc = (lane >> 4) * 4;   // ldmatrix row / word-chunk
    const int wm = (w >> 2) * 64, wn = (w & 3) * 32;
    const int m0 = blockIdx.y * 128, n0 = blockIdx.x * 128;
    const bf16* Ab = g.A + (size_t)m0 * g.lda;
    const bf16* Bb = g.Bm + (size_t)n0 * g.ldb;

    // MODE 6: tile-level Q/K select (128-wide n-tiles never straddle 512)
    const float* biasP = g.bias;
    bf16* CbP = g.Cb;
    int n0e = n0;
    if (MODE == 6 && n0 >= 512) { biasP = g.bias2; CbP = g.Cb2; n0e = n0 - 512; }

    const uint32_t aOff = ((wm + lr) * GSA + lc) * 4;
    const uint32_t bOff = ((wn + lr) * GSA + lc) * 4;

    float c[4][4][4];
    #pragma unroll
    for (int mt = 0; mt < 4; mt++)
        #pragma unroll
        for (int nt = 0; nt < 4; nt++)
            #pragma unroll
            for (int j = 0; j < 4; j++) c[mt][nt][j] = 0.0f;

    // 3-stage prologue: stages 0,1 in flight
    gload(smw, Ab, g.lda, 0);
    gload(smw + 3 * GST, Bb, g.ldb, 0);
    cp_commit();
    gload(smw + GST, Ab, g.lda, 64);
    gload(smw + 3 * GST + GST, Bb, g.ldb, 64);
    cp_commit();

    #pragma unroll 1
    for (int ch = 0; ch < NC; ch++) {
        const int st = ch % 3;
        if (ch + 1 < NC) cp_wait1(); else cp_wait0();
        __syncthreads();
        if (ch + 2 < NC) {
            const int nx = (ch + 2) % 3;
            gload(smw + nx * GST, Ab, g.lda, (ch + 2) * 64);
            gload(smw + (3 + nx) * GST, Bb, g.ldb, (ch + 2) * 64);
            cp_commit();
        }
        const uint32_t Ab_s = SB + st * (GST * 4) + aOff;
        const uint32_t Bb_s = SB + (3 + st) * (GST * 4) + bOff;
        #pragma unroll
        for (int ks = 0; ks < 4; ks++) {
            uint32_t a[4][4], b[2][4];
            #pragma unroll
            for (int mt = 0; mt < 4; mt++)
                ldsm4(a[mt], Ab_s + mt * (16 * GSA * 4) + ks * 32);
            #pragma unroll
            for (int nt2 = 0; nt2 < 2; nt2++)
                ldsm4(b[nt2], Bb_s + nt2 * (16 * GSA * 4) + ks * 32);
            #pragma unroll
            for (int mt = 0; mt < 4; mt++) {
                #pragma unroll
                for (int nt2 = 0; nt2 < 2; nt2++) {
                    uint32_t b0[2] = { b[nt2][0], b[nt2][2] };
                    uint32_t b1[2] = { b[nt2][1], b[nt2][3] };
                    mma_bf16(c[mt][nt2 * 2],     a[mt], b0);
                    mma_bf16(c[mt][nt2 * 2 + 1], a[mt], b1);
                }
            }
        }
    }

    // ------------- epilogue ---------------------------------------------------
    #pragma unroll
    for (int mt = 0; mt < 4; mt++) {
        #pragma unroll
        for (int nt = 0; nt < 4; nt++) {
            const int m = m0 + wm + mt * 16 + gq;
            const int n = n0e + wn + nt * 8 + 2 * q;
            float v00 = c[mt][nt][0], v01 = c[mt][nt][1];
            float v10 = c[mt][nt][2], v11 = c[mt][nt][3];
            if (MODE == 1) {
                float bm0 = g.bias[m], bm1 = g.bias[m + 8];
                v00 += bm0; v01 += bm0; v10 += bm1; v11 += bm1;
                // m = h*64+d (global d), n = b*512+s ; C[B,H,D,S]
                size_t base = ((size_t)(n >> 9) * 8 + (m >> 6)) * 32768 +
                              (size_t)(m & 63) * 512 + (n & 511);
                ((uint32_t*)g.Cb)[base >> 1]                = packbf(v00, v01);
                ((uint32_t*)g.Cb)[(base + 8 * 512) >> 1]    = packbf(v10, v11);
            } else {
                float bx = biasP[n], by = biasP[n + 1];
                v00 += bx; v01 += by; v10 += bx; v11 += by;
                if (MODE == 4) {
                    v00 = fmaxf(v00, 0.f); v01 = fmaxf(v01, 0.f);
                    v10 = fmaxf(v10, 0.f); v11 = fmaxf(v11, 0.f);
                }
                if (MODE == 5) {
                    const float* r0 = g.resid + (size_t)m * g.ldc + n;
                    const float* r1 = g.resid + (size_t)(m + 8) * g.ldc + n;
                    v00 += r0[0]; v01 += r0[1]; v10 += r1[0]; v11 += r1[1];
                }
                size_t e0 = (size_t)m * g.ldc + n;
                size_t e1 = (size_t)(m + 8) * g.ldc + n;
                if (MODE == 2 || MODE == 5) {
                    float2 o0 = { v00, v01 }, o1 = { v10, v11 };
                    *(float2*)(g.Cf + e0) = o0;
                    *(float2*)(g.Cf + e1) = o1;
                }
                if (MODE == 0 || MODE == 4 || MODE == 5 || MODE == 6) {
                    ((uint32_t*)CbP)[e0 >> 1] = packbf(v00, v01);
                    ((uint32_t*)CbP)[e1 >> 1] = packbf(v10, v11);
                }
            }
        }
    }
}

// ---------------- fused flash attention (bf16 + ldmatrix) ---------------------
// grid (S_/128, BH_), 256 thr. K tiles 128x64 bf16, Vt 64x128 bf16, P 128x128 bf16.
#define FSK 36
#define FSV 68
#define FSP 68
#define FL_WORDS (2*128*FSK + 2*64*FSV + 128*FSP)   /* 26624 words */
#define FL_SMEM  (FL_WORDS * 4)                      /* 106496 B */

__global__ __launch_bounds__(256) void flashB(float scale) {
    extern __shared__ uint32_t smw[];
    uint32_t* Ks[2] = { smw, smw + 128 * FSK };
    uint32_t* Vs[2] = { smw + 2 * 128 * FSK, smw + 2 * 128 * FSK + 64 * FSV };
    uint32_t* Ps = smw + 2 * 128 * FSK + 2 * 64 * FSV;
    const uint32_t PsB = smem_u32(Ps);

    const int tid = threadIdx.x, w = tid >> 5, lane = tid & 31;
    const int gq = lane >> 2, q = lane & 3;
    const int lr = lane & 15, lc = (lane >> 4) * 4;
    const int z = blockIdx.y, b = z >> 3, h = z & 7;
    const int q0 = blockIdx.x * 128;

    const bf16* Qg = g_qb + ((size_t)b * S_ + q0) * E_ + h * 64;
    const bf16* Kg = g_kb + (size_t)b * S_ * E_ + h * 64;
    const bf16* Vg = g_vtb + (size_t)z * (64 * S_);

    // stage Q (128 x 64 bf16) into Ps
    #pragma unroll
    for (int i = 0; i < 4; i++) {
        int idx = tid + i * 256;
        int r = idx >> 3, c8 = idx & 7;
        cp_async16(smem_u32(Ps + r * FSP + c8 * 4), Qg + (size_t)r * E_ + c8 * 8);
    }
    cp_commit();
    // K/V tile 0
    #pragma unroll
    for (int i = 0; i < 4; i++) {
        int idx = tid + i * 256;
        int r = idx >> 3, c8 = idx & 7;
        cp_async16(smem_u32(Ks[0] + r * FSK + c8 * 4), Kg + (size_t)r * E_ + c8 * 8);
    }
    #pragma unroll
    for (int i = 0; i < 4; i++) {
        int idx = tid + i * 256;
        int r = idx >> 4, c16 = idx & 15;
        cp_async16(smem_u32(Vs[0] + r * FSV + c16 * 4), Vg + (size_t)r * S_ + c16 * 8);
    }
    cp_commit();

    cp_wait1();
    __syncthreads();

    uint32_t qf[4][4];
    {
        uint32_t base = PsB + ((w * 16 + lr) * FSP + lc) * 4;
        #pragma unroll
        for (int ks = 0; ks < 4; ks++) ldsm4(qf[ks], base + ks * 32);
    }

    float o[8][4];
    #pragma unroll
    for (int i = 0; i < 8; i++)
        #pragma unroll
        for (int j = 0; j < 4; j++) o[i][j] = 0.0f;
    float mr0 = -1e30f, mr1 = -1e30f, l0 = 0.0f, l1 = 0.0f;

    #pragma unroll 1
    for (int kt = 0; kt < 4; kt++) {
        const int cur = kt & 1;
        cp_wait0();
        __syncthreads();
        if (kt < 3) {
            const int nxt = cur ^ 1;
            const bf16* Kn = Kg + (size_t)(kt + 1) * 128 * E_;
            #pragma unroll
            for (int i = 0; i < 4; i++) {
                int idx = tid + i * 256;
                int r = idx >> 3, c8 = idx & 7;
                cp_async16(smem_u32(Ks[nxt] + r * FSK + c8 * 4), Kn + (size_t)r * E_ + c8 * 8);
            }
            const bf16* Vn = Vg + (kt + 1) * 128;
            #pragma unroll
            for (int i = 0; i < 4; i++) {
                int idx = tid + i * 256;
                int r = idx >> 4, c16 = idx & 15;
                cp_async16(smem_u32(Vs[nxt] + r * FSV + c16 * 4), Vn + (size_t)r * S_ + c16 * 8);
            }
            cp_commit();
        }

        // ---- S = Q @ K^T ----
        const uint32_t KsB = smem_u32(Ks[cur]) + (lr * FSK + lc) * 4;
        float s[16][4];
        #pragma unroll
        for (int nf = 0; nf < 16; nf++)
            #pragma unroll
            for (int j = 0; j < 4; j++) s[nf][j] = 0.0f;
        #pragma unroll
        for (int ks = 0; ks < 4; ks++) {
            #pragma unroll
            for (int nf2 = 0; nf2 < 8; nf2++) {
                uint32_t bm[4];
                ldsm4(bm, KsB + nf2 * (16 * FSK * 4) + ks * 32);
                uint32_t b0[2] = { bm[0], bm[2] };
                uint32_t b1[2] = { bm[1], bm[3] };
                mma_bf16(s[nf2 * 2],     qf[ks], b0);
                mma_bf16(s[nf2 * 2 + 1], qf[ks], b1);
            }
        }

        // ---- scale + row max ----
        float mt0 = -1e30f, mt1 = -1e30f;
        #pragma unroll
        for (int nf = 0; nf < 16; nf++) {
            s[nf][0] *= scale; s[nf][1] *= scale;
            s[nf][2] *= scale; s[nf][3] *= scale;
            mt0 = fmaxf(mt0, fmaxf(s[nf][0], s[nf][1]));
            mt1 = fmaxf(mt1, fmaxf(s[nf][2], s[nf][3]));
        }
        mt0 = fmaxf(mt0, __shfl_xor_sync(0xFFFFFFFFu, mt0, 1));
        mt0 = fmaxf(mt0, __shfl_xor_sync(0xFFFFFFFFu, mt0, 2));
        mt1 = fmaxf(mt1, __shfl_xor_sync(0xFFFFFFFFu, mt1, 1));
        mt1 = fmaxf(mt1, __shfl_xor_sync(0xFFFFFFFFu, mt1, 2));

        float mn0 = fmaxf(mr0, mt0), mn1 = fmaxf(mr1, mt1);
        float al0 = __expf(mr0 - mn0), al1 = __expf(mr1 - mn1);

        // ---- P = exp(S-m) -> bf16 pairs into Ps (warp-local rows), row sums ----
        float sum0 = 0.0f, sum1 = 0.0f;
        int prow = (w * 16 + gq) * FSP + q;
        #pragma unroll
        for (int nf = 0; nf < 16; nf++) {
            float p0 = __expf(s[nf][0] - mn0), p1 = __expf(s[nf][1] - mn0);
            float p2 = __expf(s[nf][2] - mn1), p3 = __expf(s[nf][3] - mn1);
            sum0 += p0 + p1; sum1 += p2 + p3;
            Ps[prow + nf * 4]           = packbf(p0, p1);
            Ps[prow + nf * 4 + 8 * FSP] = packbf(p2, p3);
        }
        sum0 += __shfl_xor_sync(0xFFFFFFFFu, sum0, 1);
        sum0 += __shfl_xor_sync(0xFFFFFFFFu, sum0, 2);
        sum1 += __shfl_xor_sync(0xFFFFFFFFu, sum1, 1);
        sum1 += __shfl_xor_sync(0xFFFFFFFFu, sum1, 2);
        l0 = l0 * al0 + sum0;
        l1 = l1 * al1 + sum1;
        mr0 = mn0; mr1 = mn1;

        #pragma unroll
        for (int nf2 = 0; nf2 < 8; nf2++) {
            o[nf2][0] *= al0; o[nf2][1] *= al0;
            o[nf2][2] *= al1; o[nf2][3] *= al1;
        }
        __syncwarp();

        // ---- O += P @ V ----
        const uint32_t PsA = PsB + ((w * 16 + lr) * FSP + lc) * 4;
        const uint32_t VsB = smem_u32(Vs[cur]) + (lr * FSV + lc) * 4;
        #pragma unroll
        for (int ks2 = 0; ks2 < 8; ks2++) {
            uint32_t aa[4];
            ldsm4(aa, PsA + ks2 * 32);
            #pragma unroll
            for (int nf4 = 0; nf4 < 4; nf4++) {
                uint32_t bm[4];
                ldsm4(bm, VsB + nf4 * (16 * FSV * 4) + ks2 * 32);
                uint32_t b0[2] = { bm[0], bm[2] };
                uint32_t b1[2] = { bm[1], bm[3] };
                mma_bf16(o[nf4 * 2],     aa, b0);
                mma_bf16(o[nf4 * 2 + 1], aa, b1);
            }
        }
        __syncwarp();
    }

    // ---- epilogue: O / l -> g_catb[b, s, h*64+d] (bf16) ----
    float li0 = 1.0f / l0, li1 = 1.0f / l1;
    const int m = q0 + w * 16 + gq;
    size_t base0 = ((size_t)b * S_ + m) * E_ + h * 64 + 2 * q;
    size_t base1 = base0 + (size_t)8 * E_;
    #pragma unroll
    for (int nf2 = 0; nf2 < 8; nf2++) {
        ((uint32_t*)g_catb)[(base0 + nf2 * 8) >> 1] = packbf(o[nf2][0] * li0, o[nf2][1] * li0);
        ((uint32_t*)g_catb)[(base1 + nf2 * 8) >> 1] = packbf(o[nf2][2] * li1, o[nf2][3] * li1);
    }
}

// ---------------- weight transpose+convert: src [K,N] fp32 -> dst [N,K] bf16 --
__global__ void transpose_kernel(const float* __restrict__ src, bf16* __restrict__ dst,
                                 int K, int N) {
    __shared__ float t[32][33];
    int z = blockIdx.z;
    src += (size_t)z * K * N;
    dst += (size_t)z * N * K;
    int n0 = blockIdx.x * 32, k0 = blockIdx.y * 32;
    for (int i = threadIdx.y; i < 32; i += 8)
        t[i][threadIdx.x] = src[(size_t)(k0 + i) * N + n0 + threadIdx.x];
    __syncthreads();
    for (int i = threadIdx.y; i < 32; i += 8)
        dst[(size_t)(n0 + i) * K + k0 + threadIdx.x] = __float2bfloat16(t[threadIdx.x][i]);
}

// ---------------- embedding gather + mask (fp32 + bf16) -----------------------
__global__ void embed_kernel(const int* __restrict__ tokens, const float* __restrict__ emb) {
    int gid = blockIdx.x * 256 + threadIdx.x;   // over M*E/4
    int idx = gid * 4;
    int m = idx >> 9;
    int e = idx & 511;
    int t = tokens[m];
    float4 v = { 0.f, 0.f, 0.f, 0.f };
    if (t > 0) v = *(const float4*)(emb + (size_t)t * E_ + e);
    *(float4*)(g_out + idx) = v;
    uint2 hb = { packbf(v.x, v.y), packbf(v.z, v.w) };
    ((uint2*)g_outb)[gid] = hb;
}

// ---------------- residual add + l2 normalize (128 thr, float4) ---------------
__global__ void addnorm_kernel() {
    int row = blockIdx.x;
    float4* o4 = (float4*)(g_out + (size_t)row * E_);
    const float4* m4 = (const float4*)(g_mh + (size_t)row * E_);
    int t = threadIdx.x;
    float4 a = o4[t], m = m4[t];
    a.x += m.x; a.y += m.y; a.z += m.z; a.w += m.w;
    float sq = a.x * a.x + a.y * a.y + a.z * a.z + a.w * a.w;
    #pragma unroll
    for (int o = 16; o; o >>= 1) sq += __shfl_xor_sync(0xFFFFFFFFu, sq, o);
    __shared__ float red[4];
    if ((t & 31) == 0) red[t >> 5] = sq;
    __syncthreads();
    float inv = rsqrtf(fmaxf(red[0] + red[1] + red[2] + red[3], 1e-12f));
    a.x *= inv; a.y *= inv; a.z *= inv; a.w *= inv;
    o4[t] = a;
    uint2 hb = { packbf(a.x, a.y), packbf(a.z, a.w) };
    ((uint2*)g_outb)[(size_t)row * 128 + t] = hb;
}

// ---------------- conv1d(KW=5, stride=5) -------------------------------------
__global__ void conv_kernel(const float* __restrict__ Wc, const float* __restrict__ bc) {
    int b = blockIdx.x / LOUT_;
    int j = blockIdx.x % LOUT_;
    const float* base = g_out + ((size_t)b * S_ + j * STRIDE_) * E_;
    float acc = 0.0f;
    for (int i = threadIdx.x; i < KW_ * E_; i += 256)
        acc += base[i] * Wc[i];
    __shared__ float red[256];
    red[threadIdx.x] = acc;
    __syncthreads();
    for (int s = 128; s > 0; s >>= 1) {
        if (threadIdx.x < s) red[threadIdx.x] += red[threadIdx.x + s];
        __syncthreads();
    }
    if (threadIdx.x == 0) g_pooled[b * LOUT_ + j] = red[0] + bc[0];
}

// ---------------- final dense + softmax over 1000 ----------------------------
__global__ void dense_softmax_kernel(const float* __restrict__ Wd,
                                     const float* __restrict__ bd,
                                     float* __restrict__ outp) {
    int b = blockIdx.x;
    __shared__ float p[LOUT_];
    int t = threadIdx.x;
    if (t < LOUT_) p[t] = g_pooled[b * LOUT_ + t];
    __syncthreads();

    float lg[4];
    #pragma unroll
    for (int u = 0; u < 4; u++) {
        int o = t + u * 256;
        float acc = -1e30f;
        if (o < O_) {
            acc = bd[o];
            for (int j = 0; j < LOUT_; j++)
                acc += p[j] * Wd[j * O_ + o];
        }
        lg[u] = acc;
    }
    __shared__ float red[256];
    float m = fmaxf(fmaxf(lg[0], lg[1]), fmaxf(lg[2], lg[3]));
    red[t] = m;
    __syncthreads();
    for (int s = 128; s > 0; s >>= 1) {
        if (t < s) red[t] = fmaxf(red[t], red[t + s]);
        __syncthreads();
    }
    float mx = red[0];
    __syncthreads();
    float e[4], sum = 0.0f;
    #pragma unroll
    for (int u = 0; u < 4; u++) {
        e[u] = expf(lg[u] - mx);
        sum += e[u];
    }
    red[t] = sum;
    __syncthreads();
    for (int s = 128; s > 0; s >>= 1) {
        if (t < s) red[t] += red[t + s];
        __syncthreads();
    }
    float inv = 1.0f / red[0];
    #pragma unroll
    for (int u = 0; u < 4; u++) {
        int o = t + u * 256;
        if (o < O_) outp[(size_t)b * O_ + o] = e[u] * inv;
    }
}

// ---------------- host launcher ----------------------------------------------
extern "C" void kernel_launch(void* const* d_in, const int* in_sizes, int n_in,
                              void* d_out, int out_size) {
    const int*   tokens = (const int*)  d_in[0];
    const float* emb    = (const float*)d_in[1];
    const float* Wq     = (const float*)d_in[2];
    const float* bq     = (const float*)d_in[3];
    const float* Wk     = (const float*)d_in[4];
    const float* bk     = (const float*)d_in[5];
    const float* Wv     = (const float*)d_in[6];
    const float* bv     = (const float*)d_in[7];
    const float* Wo     = (const float*)d_in[8];
    const float* bo     = (const float*)d_in[9];
    const float* W1     = (const float*)d_in[10];
    const float* b1     = (const float*)d_in[11];
    const float* W2     = (const float*)d_in[12];
    const float* b2     = (const float*)d_in[13];
    const float* Wc     = (const float*)d_in[14];
    const float* bc     = (const float*)d_in[15];
    const float* Wd     = (const float*)d_in[16];
    const float* bd     = (const float*)d_in[17];
    float* outp = (float*)d_out;
    (void)in_sizes; (void)n_in; (void)out_size;

    float *p_out, *p_mh;
    bf16 *p_outb, *p_qb, *p_kb, *p_vtb, *p_catb, *p_ffb, *p_wtb;
    cudaGetSymbolAddress((void**)&p_out,  g_out);
    cudaGetSymbolAddress((void**)&p_mh,   g_mh);
    cudaGetSymbolAddress((void**)&p_outb, g_outb);
    cudaGetSymbolAddress((void**)&p_qb,   g_qb);
    cudaGetSymbolAddress((void**)&p_kb,   g_kb);
    cudaGetSymbolAddress((void**)&p_vtb,  g_vtb);
    cudaGetSymbolAddress((void**)&p_catb, g_catb);
    cudaGetSymbolAddress((void**)&p_ffb,  g_ffb);
    cudaGetSymbolAddress((void**)&p_wtb,  g_wtb);

    cudaFuncSetAttribute(gemmB<6,8>,  cudaFuncAttributeMaxDynamicSharedMemorySize, SMEM_G);
    cudaFuncSetAttribute(gemmB<1,8>,  cudaFuncAttributeMaxDynamicSharedMemorySize, SMEM_G);
    cudaFuncSetAttribute(gemmB<2,8>,  cudaFuncAttributeMaxDynamicSharedMemorySize, SMEM_G);
    cudaFuncSetAttribute(gemmB<4,8>,  cudaFuncAttributeMaxDynamicSharedMemorySize, SMEM_G);
    cudaFuncSetAttribute(gemmB<5,16>, cudaFuncAttributeMaxDynamicSharedMemorySize, SMEM_G);
    cudaFuncSetAttribute(flashB,      cudaFuncAttributeMaxDynamicSharedMemorySize, FL_SMEM);

    const float scale = 0.044194173824159216f;  // 1/sqrt(512)
    dim3 tthr(32, 8);

    // ---- pre-transpose+convert all weights to bf16 [N,K] ----
    for (int i = 0; i < L_; i++) {
        bf16* wt = p_wtb + (size_t)i * LWT_;
        transpose_kernel<<<dim3(2, 16, 8), tthr>>>(Wq + (size_t)i*H_*E_*D_, wt + QT_,  512, 64);
        transpose_kernel<<<dim3(2, 16, 8), tthr>>>(Wk + (size_t)i*H_*E_*D_, wt + KT_,  512, 64);
        transpose_kernel<<<dim3(2, 16, 8), tthr>>>(Wv + (size_t)i*H_*E_*D_, wt + VTW_, 512, 64);
        transpose_kernel<<<dim3(16, 16, 1), tthr>>>(Wo + (size_t)i*E_*E_,   wt + OT_,  512, 512);
        transpose_kernel<<<dim3(32, 16, 1), tthr>>>(W1 + (size_t)i*E_*2*E_, wt + W1T_, 512, 1024);
        transpose_kernel<<<dim3(16, 32, 1), tthr>>>(W2 + (size_t)i*2*E_*E_, wt + W2T_, 1024, 512);
    }

    embed_kernel<<<(M_ * E_) / 1024, 256>>>(tokens, emb);

    for (int i = 0; i < L_; i++) {
        bf16* wt = p_wtb + (size_t)i * LWT_;
        GB a;

        // Q|K = out @ [Wq|Wk]^T + [bq|bk]  -> bf16, one N=1024 launch
        a = { p_outb, wt + QT_, bq + (size_t)i*512, nullptr, nullptr, p_qb,
              bk + (size_t)i*512, p_kb, 512, 512, 512 };
        gemmB<6,8><<<dim3(8, 256), 256, SMEM_G>>>(a);
        // V^T = Wv^T @ out^T + bv  -> bf16 [B,H,D,S]  (A=weights, B=activations)
        a = { wt + VTW_, p_outb, bv + (size_t)i*512, nullptr, nullptr, p_vtb,
              nullptr, nullptr, 512, 512, 0 };
        gemmB<1,8><<<dim3(256, 4), 256, SMEM_G>>>(a);

        // fused attention -> g_catb (bf16)
        flashB<<<dim3(S_/128, BH_), 256, FL_SMEM>>>(scale);

        // mh = cat @ Wo^T + bo  -> fp32
        a = { p_catb, wt + OT_, bo + (size_t)i*512, nullptr, p_mh, nullptr,
              nullptr, nullptr, 512, 512, 512 };
        gemmB<2,8><<<dim3(4, 256), 256, SMEM_G>>>(a);

        addnorm_kernel<<<M_, 128>>>();

        // ff = relu(out @ W1^T + b1)  -> bf16
        a = { p_outb, wt + W1T_, b1 + (size_t)i*1024, nullptr, nullptr, p_ffb,
              nullptr, nullptr, 512, 512, 1024 };
        gemmB<4,8><<<dim3(8, 256), 256, SMEM_G>>>(a);

        // out = ff @ W2^T + b2 + out  -> fp32 + bf16
        a = { p_ffb, wt + W2T_, b2 + (size_t)i*512, p_out, p_out, p_outb,
              nullptr, nullptr, 1024, 1024, 512 };
        gemmB<5,16><<<dim3(4, 256), 256, SMEM_G>>>(a);
    }

    conv_kernel<<<B_ * LOUT_, 256>>>(Wc, bc);
    dense_softmax_kernel<<<B_, 256>>>(Wd, bd, outp);
}